// round 9
// baseline (speedup 1.0000x reference)
#include <cuda_runtime.h>
#include <cstdint>

// Problem shape (fixed by the reference)
#define BB 64
#define SS 2048
#define DD 256
#define CTAS_PER_B 8
#define ROWS_PER_CTA (SS / CTAS_PER_B)      // 256
#define WARPS 8
#define ROWS_PER_WARP (ROWS_PER_CTA / WARPS) // 32
#define TROWS 4
#define TBYTES (TROWS * DD * 4)              // 4096
#define NTILES (ROWS_PER_WARP / TROWS)       // 8
#define NSLOT 3
#define GRIDX (BB * CTAS_PER_B)              // 512 CTAs

// smem: per-warp rings [8 warps][3 slots][4096 B] = 96 KB, then mbarriers.
// The reduce arrays alias the ring region (used only after __syncthreads when
// every issued copy has been consumed).
#define RING_SZ (WARPS * NSLOT * TBYTES)
#define SM_MBAR RING_SZ
#define SM_TOTAL (RING_SZ + WARPS * NSLOT * 8 + 64)

// Global scratch (zero-init; finalizing CTA resets for graph replays)
__device__ float    g_sum [BB * DD];
__device__ unsigned g_maxo[BB * DD];
__device__ float    g_cnt [BB];
__device__ int      g_arrived[BB];

__device__ __forceinline__ float neg_inf() { return __int_as_float(0xff800000); }
__device__ __forceinline__ unsigned f2o(float f) {
    unsigned u = __float_as_uint(f);
    return (u & 0x80000000u) ? ~u : (u | 0x80000000u);
}
__device__ __forceinline__ float o2f(unsigned u) {
    return __uint_as_float((u & 0x80000000u) ? (u & 0x7fffffffu) : ~u);
}
__device__ __forceinline__ int arrive_acq_rel(int* addr) {
    int old;
    asm volatile("atom.add.acq_rel.gpu.global.s32 %0, [%1], 1;"
                 : "=r"(old) : "l"(addr) : "memory");
    return old;
}
__device__ __forceinline__ uint32_t smem_u32(const void* p) {
    uint32_t a;
    asm("{ .reg .u64 t; cvta.to.shared.u64 t, %1; cvt.u32.u64 %0, t; }" : "=r"(a) : "l"(p));
    return a;
}
__device__ __forceinline__ void mbar_init(uint32_t bar, uint32_t cnt) {
    asm volatile("mbarrier.init.shared.b64 [%0], %1;" :: "r"(bar), "r"(cnt) : "memory");
}
__device__ __forceinline__ void mbar_expect_tx(uint32_t bar, uint32_t bytes) {
    asm volatile("mbarrier.arrive.expect_tx.shared.b64 _, [%0], %1;"
                 :: "r"(bar), "r"(bytes) : "memory");
}
__device__ __forceinline__ void mbar_wait(uint32_t bar, uint32_t parity) {
    asm volatile(
        "{\n\t"
        ".reg .pred P;\n\t"
        "WL_%=:\n\t"
        "mbarrier.try_wait.parity.acquire.cta.shared::cta.b64 P, [%0], %1, 0x989680;\n\t"
        "@P bra.uni WD_%=;\n\t"
        "bra.uni WL_%=;\n\t"
        "WD_%=:\n\t"
        "}" :: "r"(bar), "r"(parity) : "memory");
}
__device__ __forceinline__ void bulk_g2s(uint32_t dst, const void* src,
                                         uint32_t bytes, uint32_t bar) {
    asm volatile(
        "cp.async.bulk.shared::cta.global.mbarrier::complete_tx::bytes [%0], [%1], %2, [%3];"
        :: "r"(dst), "l"(src), "r"(bytes), "r"(bar) : "memory");
}

// Warp-autonomous TMA ring: each warp streams 32 rows as 8 tiles of 4 rows
// through 3 private 4 KB slots. No CTA-wide syncs in the stream loop.
__global__ void __launch_bounds__(256, 2)
pool_tma_warp(const float* __restrict__ feats,
              const float* __restrict__ mask,
              float* __restrict__ out) {
    extern __shared__ char smem[];
    const int tid  = threadIdx.x;
    const int w    = tid >> 5;
    const int lane = tid & 31;
    const int cta  = blockIdx.x;
    const int b    = cta / CTAS_PER_B;
    const int q    = cta % CTAS_PER_B;
    const int rs   = q * ROWS_PER_CTA + w * ROWS_PER_WARP;  // row within batch b
    const size_t gbase = (size_t)b * SS;

    const uint32_t smb  = smem_u32(smem);
    const uint32_t ring = smb + (uint32_t)(w * NSLOT) * TBYTES;
    const uint32_t bar0 = smb + SM_MBAR + (uint32_t)(w * NSLOT) * 8;

    if (tid < WARPS * NSLOT) mbar_init(smb + SM_MBAR + tid * 8, 1);
    __syncthreads();

    // Lane owns float4 columns `lane` and `lane+32` of each row (D=256 -> 64 float4)
    float4 sum0 = make_float4(0.f, 0.f, 0.f, 0.f), sum1 = sum0;
    float4 mx0  = make_float4(neg_inf(), neg_inf(), neg_inf(), neg_inf()), mx1 = mx0;
    float  cnt  = 0.f;

    float    mv [NSLOT];   // lanes 0..3: mask of row r of the in-flight tile
    unsigned bal[NSLOT];   // warp-uniform validity bitmap (4 bits)
    int      ph [NSLOT] = {0, 0, 0};

    // Issue tile t into slot t%NSLOT (mask-gated).
    auto issue = [&](int t) {
        const int slot = t % NSLOT;
        const int r0   = rs + t * TROWS;
        float m = (lane < TROWS) ? __ldca(mask + gbase + r0 + lane) : 0.f;
        unsigned blv = __ballot_sync(0xffffffffu, m > 0.f) & 0xFu;
        cnt += m;                       // lanes >= 4 add 0; skipped tiles add 0
        mv [slot] = m;
        bal[slot] = blv;
        if (blv && lane == 0) {
            mbar_expect_tx(bar0 + slot * 8, TBYTES);
            bulk_g2s(ring + slot * TBYTES,
                     feats + (gbase + r0) * DD, TBYTES, bar0 + slot * 8);
        }
    };

#pragma unroll
    for (int t = 0; t < NSLOT; ++t) issue(t);

#pragma unroll
    for (int t = 0; t < NTILES; ++t) {
        const int slot = t % NSLOT;
        const unsigned blv = bal[slot];
        float m0 = __shfl_sync(0xffffffffu, mv[slot], 0);
        float m1 = __shfl_sync(0xffffffffu, mv[slot], 1);
        float m2 = __shfl_sync(0xffffffffu, mv[slot], 2);
        float m3 = __shfl_sync(0xffffffffu, mv[slot], 3);

        if (blv) {
            mbar_wait(bar0 + slot * 8, ph[slot]);
            ph[slot] ^= 1;
            const float4* __restrict__ fs =
                reinterpret_cast<const float4*>(smem + (w * NSLOT + slot) * TBYTES);
            const float mm[4] = {m0, m1, m2, m3};
            if (blv == 0xFu) {
#pragma unroll
                for (int r = 0; r < TROWS; ++r) {
                    const float  m = mm[r];
                    const float4 a = fs[r * 64 + lane];
                    const float4 c = fs[r * 64 + lane + 32];
                    sum0.x += a.x * m; sum0.y += a.y * m;
                    sum0.z += a.z * m; sum0.w += a.w * m;
                    sum1.x += c.x * m; sum1.y += c.y * m;
                    sum1.z += c.z * m; sum1.w += c.w * m;
                    mx0.x = fmaxf(mx0.x, a.x); mx0.y = fmaxf(mx0.y, a.y);
                    mx0.z = fmaxf(mx0.z, a.z); mx0.w = fmaxf(mx0.w, a.w);
                    mx1.x = fmaxf(mx1.x, c.x); mx1.y = fmaxf(mx1.y, c.y);
                    mx1.z = fmaxf(mx1.z, c.z); mx1.w = fmaxf(mx1.w, c.w);
                }
            } else {
#pragma unroll
                for (int r = 0; r < TROWS; ++r) {
                    const float  m = mm[r];
                    const bool   v = (m > 0.f);
                    const float4 a = fs[r * 64 + lane];
                    const float4 c = fs[r * 64 + lane + 32];
                    sum0.x += a.x * m; sum0.y += a.y * m;
                    sum0.z += a.z * m; sum0.w += a.w * m;
                    sum1.x += c.x * m; sum1.y += c.y * m;
                    sum1.z += c.z * m; sum1.w += c.w * m;
                    mx0.x = fmaxf(mx0.x, v ? a.x : neg_inf());
                    mx0.y = fmaxf(mx0.y, v ? a.y : neg_inf());
                    mx0.z = fmaxf(mx0.z, v ? a.z : neg_inf());
                    mx0.w = fmaxf(mx0.w, v ? a.w : neg_inf());
                    mx1.x = fmaxf(mx1.x, v ? c.x : neg_inf());
                    mx1.y = fmaxf(mx1.y, v ? c.y : neg_inf());
                    mx1.z = fmaxf(mx1.z, v ? c.z : neg_inf());
                    mx1.w = fmaxf(mx1.w, v ? c.w : neg_inf());
                }
            }
        }
        if (t + NSLOT < NTILES) issue(t + NSLOT);   // reuse just-consumed slot
    }

    // Sum cnt over lanes 0..3 (other lanes hold 0)
    cnt += __shfl_xor_sync(0xffffffffu, cnt, 1);
    cnt += __shfl_xor_sync(0xffffffffu, cnt, 2);

    // CTA reduce: ring smem is dead now (every issued copy consumed) — alias it.
    __syncthreads();
    float4* s_sum = reinterpret_cast<float4*>(smem);            // [8][64]
    float4* s_max = reinterpret_cast<float4*>(smem + 8192);     // [8][64]
    float*  s_cnt = reinterpret_cast<float*>(smem + 16384);     // [8]
    int*    s_last = reinterpret_cast<int*>(smem + 16384 + 32);
    s_sum[w * 64 + lane]      = sum0;
    s_sum[w * 64 + lane + 32] = sum1;
    s_max[w * 64 + lane]      = mx0;
    s_max[w * 64 + lane + 32] = mx1;
    if (lane == 0) s_cnt[w] = cnt;
    __syncthreads();

    if (tid < 64) {
        float4 a = s_sum[tid];
        float4 m = s_max[tid];
#pragma unroll
        for (int k = 1; k < WARPS; ++k) {
            float4 a2 = s_sum[k * 64 + tid];
            float4 m2 = s_max[k * 64 + tid];
            a.x += a2.x; a.y += a2.y; a.z += a2.z; a.w += a2.w;
            m.x = fmaxf(m.x, m2.x); m.y = fmaxf(m.y, m2.y);
            m.z = fmaxf(m.z, m2.z); m.w = fmaxf(m.w, m2.w);
        }
        const int dbase = b * DD + tid * 4;
        atomicAdd(&g_sum[dbase + 0], a.x);
        atomicAdd(&g_sum[dbase + 1], a.y);
        atomicAdd(&g_sum[dbase + 2], a.z);
        atomicAdd(&g_sum[dbase + 3], a.w);
        atomicMax(&g_maxo[dbase + 0], f2o(m.x));
        atomicMax(&g_maxo[dbase + 1], f2o(m.y));
        atomicMax(&g_maxo[dbase + 2], f2o(m.z));
        atomicMax(&g_maxo[dbase + 3], f2o(m.w));
        if (tid == 0) {
            float c = 0.f;
#pragma unroll
            for (int k = 0; k < WARPS; ++k) c += s_cnt[k];
            atomicAdd(&g_cnt[b], c);
        }
    }

    // Arrival: syncthreads orders all flushes before tid0's acq_rel add.
    __syncthreads();
    if (tid == 0)
        *s_last = (arrive_acq_rel(&g_arrived[b]) == CTAS_PER_B - 1);
    __syncthreads();
    if (!*s_last) return;

    // Finalizer for this b: write output, reset scratch for next replay.
    {
        const int d = tid;  // 0..255
        float    fsum = __ldcg(&g_sum[b * DD + d]);
        unsigned mo   = __ldcg(&g_maxo[b * DD + d]);
        float    fcnt = __ldcg(&g_cnt[b]);
        out[(size_t)b * (2 * DD) + d]      = o2f(mo);
        out[(size_t)b * (2 * DD) + DD + d] = fsum / fcnt;
        __stcg(&g_sum[b * DD + d], 0.f);
        __stcg(&g_maxo[b * DD + d], 0u);
        if (tid == 0) {
            __stcg(&g_cnt[b], 0.f);
            __stcg(&g_arrived[b], 0);
        }
    }
}

extern "C" void kernel_launch(void* const* d_in, const int* in_sizes, int n_in,
                              void* d_out, int out_size) {
    const float* feats = (const float*)d_in[0];
    const float* mask  = (const float*)d_in[1];
    float* out = (float*)d_out;

    cudaFuncSetAttribute(pool_tma_warp,
                         cudaFuncAttributeMaxDynamicSharedMemorySize, SM_TOTAL);
    pool_tma_warp<<<GRIDX, 256, SM_TOTAL>>>(feats, mask, out);
}